// round 10
// baseline (speedup 1.0000x reference)
#include <cuda_runtime.h>
#include <cstdint>

// Conv2d VALID: x[32,64,112,112] f32, w[128,64,3,3] f32 -> out[32,128,110,110] f32
// Implicit GEMM, mma.sync.m16n8k8 tf32.
// Round 9: R5/R6 hybrid. CTA 128m x 128n (2 oh x 64 ow), 8 warps (2m x 4n) of
// 64x32. Input window (32ch x 4row x 66col) staged ONCE per ci-half,
// pre-converted to tf32 at staging. A chunks double-buffered from pre-permuted
// global. Warp-staggered k-group order to keep the tensor pipe fed.

namespace {

constexpr int CIN = 64, COUT = 128, H = 112, W = 112, OH = 110, OW = 110;
constexpr int A_STRIDE = 36;                 // floats per A row (32 + 4 pad)
constexpr int X_KSTRIDE = 264;               // 4*66; 264 % 32 == 8 -> conflict-free B LDS
constexpr int SM_X_FLOATS = 32 * X_KSTRIDE;  // 8448
constexpr int SM_A_FLOATS = 128 * A_STRIDE;  // 4608
constexpr int SM_TOTAL = (SM_X_FLOATS + 2 * SM_A_FLOATS) * 4;  // 70656 B

__device__ float g_A_pre[18 * 4096];  // [kc][co 128][perm-col 32], tf32

__device__ __forceinline__ float to_tf32(float v) {
    float o;
    asm("cvt.rna.tf32.f32 %0, %1;" : "=f"(o) : "f"(v));
    return o;
}

// perm-col = g*8 + q*2 + e  <->  k = g*8 + q + 4*e
__global__ void prep_weights(const float* __restrict__ w) {
    int idx = blockIdx.x * 256 + threadIdx.x;  // 0 .. 73727
    int kc  = idx >> 12;
    int rem = idx & 4095;
    int co  = rem >> 5;
    int col = rem & 31;
    int g = col >> 3, tt = col & 7, q = tt >> 1, e = tt & 1;
    int k  = g * 8 + q + 4 * e;
    int h  = kc / 9;
    int rs = kc - h * 9;
    int ci = h * 32 + k;
    g_A_pre[idx] = to_tf32(w[((size_t)co * CIN + ci) * 9 + rs]);
}

__global__ __launch_bounds__(256, 2)
void conv_mma(const float* __restrict__ x, float* __restrict__ out)
{
    extern __shared__ float sm[];
    float* Xs = sm;                                  // [k*264 + row*66 + col], tf32
    float* Abuf[2] = { sm + SM_X_FLOATS, sm + SM_X_FLOATS + SM_A_FLOATS };

    const int tid  = threadIdx.x;
    const int wid  = tid >> 5;
    const int lane = tid & 31;
    const int wm   = wid >> 2;        // 0..1 (m half)
    const int wn   = wid & 3;         // 0..3 (n quarter)
    const int lr   = lane >> 2;       // 0..7
    const int lq   = lane & 3;        // 0..3

    const int ow0 = blockIdx.x * 64;
    const int oh0 = blockIdx.y * 2;
    const int bb  = blockIdx.z;

    float acc[4][4][4];
#pragma unroll
    for (int i = 0; i < 4; i++)
#pragma unroll
        for (int j = 0; j < 4; j++)
#pragma unroll
            for (int k = 0; k < 4; k++) acc[i][j][k] = 0.0f;

    const float* xb = x + (size_t)bb * CIN * H * W;

    // preload A chunk 0 into buf 0
    {
        const float4* src = (const float4*)g_A_pre;
#pragma unroll
        for (int i = 0; i < 4; ++i) {
            int idx = tid + 256 * i;
            float4 v = src[idx];
            *(float4*)(Abuf[0] + (idx >> 3) * A_STRIDE + (idx & 7) * 4) = v;
        }
    }

    const int osub  = wn >> 1;           // warp's output sub-row (0/1)
    const int cbase = (wn & 1) * 32;     // warp's column base within 64

    for (int h = 0; h < 2; ++h) {
        __syncthreads();   // previous half's compute done before Xs overwrite

        // ---- stage raw input window, pre-converted to tf32 ----
#pragma unroll
        for (int i = 0; i < 33; ++i) {
            int flat = tid + 256 * i;                 // == k*264 + row*66 + col
            int k    = flat / X_KSTRIDE;
            int rem  = flat - k * X_KSTRIDE;
            int row  = rem / 66;
            int col  = rem - row * 66;
            int iw   = ow0 + col;
            float v  = 0.0f;
            if (iw < W)
                v = to_tf32(xb[((size_t)(h * 32 + k) * H + (oh0 + row)) * W + iw]);
            Xs[flat] = v;
        }
        __syncthreads();   // Xs + current A chunk visible

        for (int t = 0; t < 9; ++t) {
            const int kc = h * 9 + t;
            const int r  = t / 3;
            const int s  = t - r * 3;

            // ---- prefetch next A chunk into other buffer ----
            if (kc < 17) {
                const float4* src = (const float4*)(g_A_pre + (kc + 1) * 4096);
                float* dst = Abuf[(kc + 1) & 1];
#pragma unroll
                for (int i = 0; i < 4; ++i) {
                    int idx = tid + 256 * i;
                    float4 v = src[idx];
                    *(float4*)(dst + (idx >> 3) * A_STRIDE + (idx & 7) * 4) = v;
                }
            }

            // ---- compute tap; k-group order staggered by warp id ----
            const float* Ab = Abuf[kc & 1];
            const float* xw = Xs + (osub + r) * 66 + cbase + s;

#pragma unroll
            for (int gi = 0; gi < 4; ++gi) {
                const int g = (gi + wid) & 3;
                uint32_t a[4][4];
#pragma unroll
                for (int mf = 0; mf < 4; ++mf) {
                    int row = wm * 64 + mf * 16 + lr;
                    float2 v02 = *(const float2*)(Ab + row * A_STRIDE + g * 8 + lq * 2);
                    float2 v13 = *(const float2*)(Ab + (row + 8) * A_STRIDE + g * 8 + lq * 2);
                    a[mf][0] = __float_as_uint(v02.x);
                    a[mf][1] = __float_as_uint(v13.x);
                    a[mf][2] = __float_as_uint(v02.y);
                    a[mf][3] = __float_as_uint(v13.y);
                }
                uint32_t b[4][2];
#pragma unroll
                for (int nf = 0; nf < 4; ++nf) {
                    // bank = 8*lq + lr + const  -> conflict-free
                    b[nf][0] = __float_as_uint(xw[(g * 8 + lq) * X_KSTRIDE + nf * 8 + lr]);
                    b[nf][1] = __float_as_uint(xw[(g * 8 + lq + 4) * X_KSTRIDE + nf * 8 + lr]);
                }
#pragma unroll
                for (int mf = 0; mf < 4; ++mf)
#pragma unroll
                    for (int nf = 0; nf < 4; ++nf) {
                        asm volatile(
                            "mma.sync.aligned.m16n8k8.row.col.f32.tf32.tf32.f32 "
                            "{%0,%1,%2,%3}, {%4,%5,%6,%7}, {%8,%9}, {%0,%1,%2,%3};"
                            : "+f"(acc[mf][nf][0]), "+f"(acc[mf][nf][1]),
                              "+f"(acc[mf][nf][2]), "+f"(acc[mf][nf][3])
                            : "r"(a[mf][0]), "r"(a[mf][1]), "r"(a[mf][2]), "r"(a[mf][3]),
                              "r"(b[nf][0]), "r"(b[nf][1]));
                    }
            }

            if (t < 8) __syncthreads();   // before next A STS overwrite
        }
    }

    // ---- epilogue: direct STG.64 (even ow, pairs in-bounds) ----
#pragma unroll
    for (int mf = 0; mf < 4; ++mf) {
#pragma unroll
        for (int nf = 0; nf < 4; ++nf) {
            int nglob = wn * 32 + nf * 8 + lq * 2;    // even
            int os    = nglob >> 6;
            int ow    = ow0 + (nglob & 63);
            int oh    = oh0 + os;
            if (ow < OW) {
                int co0 = wm * 64 + mf * 16 + lr;
                float* p0 = out + (((size_t)bb * COUT + co0) * OH + oh) * OW + ow;
                *(float2*)p0 = make_float2(acc[mf][nf][0], acc[mf][nf][1]);
                float* p1 = p0 + (size_t)8 * OH * OW;
                *(float2*)p1 = make_float2(acc[mf][nf][2], acc[mf][nf][3]);
            }
        }
    }
}

} // namespace

extern "C" void kernel_launch(void* const* d_in, const int* in_sizes, int n_in,
                              void* d_out, int out_size)
{
    const float* x = (const float*)d_in[0];
    const float* w = (const float*)d_in[1];
    float* out = (float*)d_out;

    cudaFuncSetAttribute(conv_mma, cudaFuncAttributeMaxDynamicSharedMemorySize, SM_TOTAL);

    prep_weights<<<18 * 4096 / 256, 256>>>(w);

    dim3 grid(2, 55, 32);   // ow tiles, oh pairs, batch
    conv_mma<<<grid, 256, SM_TOTAL>>>(x, out);
}

// round 11
// speedup vs baseline: 1.5048x; 1.5048x over previous
#include <cuda_runtime.h>
#include <cstdint>

// Conv2d VALID: x[32,64,112,112] f32, w[128,64,3,3] f32 -> out[32,128,110,110] f32
// Implicit GEMM, mma.sync.m16n8k8 tf32.
// Round 11: R5 skeleton (CTA 128m x 128n = 2 oh x 64 ow, 8 warps of 64x32,
// 2 CTA/SM) + input window staged ONCE per ci-half as tf32 (k,k+4) float2
// pairs with a conflict-free paired layout (KP=17), A_STRIDE=40 (conflict-free
// A frags), cvt at staging only, all inner addresses compile-time affine.

namespace {

constexpr int CIN = 64, COUT = 128, H = 112, W = 112, OH = 110, OW = 110;
constexpr int A_STRIDE = 40;                 // floats per A row: pair-bank = 4*lr+lq (bijective)
constexpr int SM_A_FLOATS = 128 * A_STRIDE;  // 5120
constexpr int XS_KP = 17;                    // float2 per cell: 16 + 1 pad -> pair-bank lr+4*lq
constexpr int XS_CELLS = 4 * 66;             // 4 rows x 66 cols
constexpr int XS_F2 = XS_CELLS * XS_KP;      // 4488 float2
constexpr int SM_TOTAL = (2 * SM_A_FLOATS + 2 * XS_F2) * 4;   // 76864 B

__device__ float g_A_pre[18 * 4096];  // [kc][co 128][perm-col 32], tf32

__device__ __forceinline__ float to_tf32(float v) {
    float o;
    asm("cvt.rna.tf32.f32 %0, %1;" : "=f"(o) : "f"(v));
    return o;
}

// perm-col = g*8 + q*2 + e  <->  k = g*8 + q + 4*e
__global__ void prep_weights(const float* __restrict__ w) {
    int idx = blockIdx.x * 256 + threadIdx.x;  // 0 .. 73727
    int kc  = idx >> 12;
    int rem = idx & 4095;
    int co  = rem >> 5;
    int col = rem & 31;
    int g = col >> 3, tt = col & 7, q = tt >> 1, e = tt & 1;
    int k  = g * 8 + q + 4 * e;
    int h  = kc / 9;
    int rs = kc - h * 9;
    int ci = h * 32 + k;
    g_A_pre[idx] = to_tf32(w[((size_t)co * CIN + ci) * 9 + rs]);
}

__global__ __launch_bounds__(256, 2)
void conv_mma(const float* __restrict__ x, float* __restrict__ out)
{
    extern __shared__ float sm[];
    float*  Abuf[2] = { sm, sm + SM_A_FLOATS };
    float2* Xs2     = (float2*)(sm + 2 * SM_A_FLOATS);   // [cell*17 + kp], kp=q*4+g

    const int tid  = threadIdx.x;
    const int wid  = tid >> 5;
    const int lane = tid & 31;
    const int wm   = wid >> 2;        // 0..1 (m half)
    const int wn   = wid & 3;         // 0..3 (n quarter)
    const int lr   = lane >> 2;       // 0..7
    const int lq   = lane & 3;        // 0..3

    const int ow0 = blockIdx.x * 64;
    const int oh0 = blockIdx.y * 2;
    const int bb  = blockIdx.z;

    float acc[4][4][4];
#pragma unroll
    for (int i = 0; i < 4; i++)
#pragma unroll
        for (int j = 0; j < 4; j++)
#pragma unroll
            for (int k = 0; k < 4; k++) acc[i][j][k] = 0.0f;

    const float* xb = x + (size_t)bb * CIN * H * W;

    // preload A chunk 0 into buf 0
    {
        const float4* src = (const float4*)g_A_pre;
#pragma unroll
        for (int i = 0; i < 4; ++i) {
            int idx = tid + 256 * i;
            float4 v = src[idx];
            *(float4*)(Abuf[0] + (idx >> 3) * A_STRIDE + (idx & 7) * 4) = v;
        }
    }

    const int osub  = wn >> 1;           // warp's output sub-row (0/1)
    const int cbase = (wn & 1) * 32;     // warp's column base within 64

    for (int h = 0; h < 2; ++h) {
        __syncthreads();   // previous half's compute done before Xs overwrite

        // ---- stage input window as tf32 (k,k+4) float2 pairs ----
        // flat = kp*264 + cell  (cell = row*66 + col): col-fastest -> coalesced LDG
#pragma unroll
        for (int i = 0; i < 17; ++i) {
            int flat = tid + 256 * i;
            if (flat < 16 * XS_CELLS) {
                int kp   = flat / XS_CELLS;
                int cell = flat - kp * XS_CELLS;
                int row  = cell / 66;
                int col  = cell - row * 66;
                int q    = kp >> 2;
                int g    = kp & 3;
                int ch   = h * 32 + g * 8 + q;
                int iw   = ow0 + col;
                float v0 = 0.0f, v1 = 0.0f;
                if (iw < W) {
                    const float* p = xb + ((size_t)ch * H + (oh0 + row)) * W + iw;
                    v0 = to_tf32(p[0]);
                    v1 = to_tf32(p[4 * H * W]);   // k + 4
                }
                Xs2[cell * XS_KP + kp] = make_float2(v0, v1);
            }
        }
        __syncthreads();   // Xs + current A chunk visible

        for (int t = 0; t < 9; ++t) {
            const int kc = h * 9 + t;
            const int r  = t / 3;
            const int s  = t - r * 3;

            if (t > 0) __syncthreads();   // prev tap's A reads done before overwrite

            // ---- prefetch next A chunk into other buffer ----
            if (kc < 17) {
                const float4* src = (const float4*)(g_A_pre + (kc + 1) * 4096);
                float* dst = Abuf[(kc + 1) & 1];
#pragma unroll
                for (int i = 0; i < 4; ++i) {
                    int idx = tid + 256 * i;
                    float4 v = src[idx];
                    *(float4*)(dst + (idx >> 3) * A_STRIDE + (idx & 7) * 4) = v;
                }
            }

            // ---- compute tap ----
            const float*  Ab = Abuf[kc & 1];
            const float2* xw = Xs2 + ((osub + r) * 66 + cbase + s) * XS_KP + lq * 4;

#pragma unroll
            for (int g = 0; g < 4; ++g) {
                uint32_t a[4][4];
#pragma unroll
                for (int mf = 0; mf < 4; ++mf) {
                    int row = wm * 64 + mf * 16 + lr;
                    float2 v02 = *(const float2*)(Ab + row * A_STRIDE + g * 8 + lq * 2);
                    float2 v13 = *(const float2*)(Ab + (row + 8) * A_STRIDE + g * 8 + lq * 2);
                    a[mf][0] = __float_as_uint(v02.x);
                    a[mf][1] = __float_as_uint(v13.x);
                    a[mf][2] = __float_as_uint(v02.y);
                    a[mf][3] = __float_as_uint(v13.y);
                }
                uint32_t b[4][2];
#pragma unroll
                for (int nf = 0; nf < 4; ++nf) {
                    float2 v = xw[(nf * 8 + lr) * XS_KP + g];   // kp = lq*4 + g
                    b[nf][0] = __float_as_uint(v.x);
                    b[nf][1] = __float_as_uint(v.y);
                }
#pragma unroll
                for (int mf = 0; mf < 4; ++mf)
#pragma unroll
                    for (int nf = 0; nf < 4; ++nf) {
                        asm volatile(
                            "mma.sync.aligned.m16n8k8.row.col.f32.tf32.tf32.f32 "
                            "{%0,%1,%2,%3}, {%4,%5,%6,%7}, {%8,%9}, {%0,%1,%2,%3};"
                            : "+f"(acc[mf][nf][0]), "+f"(acc[mf][nf][1]),
                              "+f"(acc[mf][nf][2]), "+f"(acc[mf][nf][3])
                            : "r"(a[mf][0]), "r"(a[mf][1]), "r"(a[mf][2]), "r"(a[mf][3]),
                              "r"(b[nf][0]), "r"(b[nf][1]));
                    }
            }
        }
    }

    // ---- epilogue: direct STG.64 (even ow, pairs in-bounds) ----
#pragma unroll
    for (int mf = 0; mf < 4; ++mf) {
#pragma unroll
        for (int nf = 0; nf < 4; ++nf) {
            int nglob = wn * 32 + nf * 8 + lq * 2;    // even
            int os    = nglob >> 6;
            int ow    = ow0 + (nglob & 63);
            int oh    = oh0 + os;
            if (ow < OW) {
                int co0 = wm * 64 + mf * 16 + lr;
                float* p0 = out + (((size_t)bb * COUT + co0) * OH + oh) * OW + ow;
                *(float2*)p0 = make_float2(acc[mf][nf][0], acc[mf][nf][1]);
                float* p1 = p0 + (size_t)8 * OH * OW;
                *(float2*)p1 = make_float2(acc[mf][nf][2], acc[mf][nf][3]);
            }
        }
    }
}

} // namespace

extern "C" void kernel_launch(void* const* d_in, const int* in_sizes, int n_in,
                              void* d_out, int out_size)
{
    const float* x = (const float*)d_in[0];
    const float* w = (const float*)d_in[1];
    float* out = (float*)d_out;

    cudaFuncSetAttribute(conv_mma, cudaFuncAttributeMaxDynamicSharedMemorySize, SM_TOTAL);

    prep_weights<<<18 * 4096 / 256, 256>>>(w);

    dim3 grid(2, 55, 32);   // ow tiles, oh pairs, batch
    conv_mma<<<grid, 256, SM_TOTAL>>>(x, out);
}

// round 12
// speedup vs baseline: 2.1212x; 1.4096x over previous
#include <cuda_runtime.h>
#include <cstdint>

// Conv2d VALID: x[32,64,112,112] f32, w[128,64,3,3] f32 -> out[32,128,110,110] f32
// Implicit GEMM via mma.sync.m16n8k8 tf32.
// Round 12: exact R5 skeleton (per-chunk im2col LDG gather, 18 chunks of 32,
// CTA 128m x 128n = 2 oh x 64 ow, 8 warps of 64x32, 2 CTA/SM) with both
// fragment-LDS paths made conflict-free:
//   A: A_STRIDE=40  -> pair-bank (4*lr+lq) bijective per half-warp
//   B: Bs[n*17+kp], kp=q*4+g -> STS and LDS both bijective per half-warp

namespace {

constexpr int CIN = 64, COUT = 128, H = 112, W = 112, OH = 110, OW = 110;
constexpr int NCHUNK = 18;
constexpr int A_STRIDE = 40;          // floats per A row (32 + 8 pad)
constexpr int B_KP = 17;              // float2 per n: 16 kp + 1 pad

__device__ float g_A_pre[NCHUNK * 4096];   // [kc][co 128][perm-col 32] tf32

__device__ __forceinline__ float to_tf32(float v) {
    float o;
    asm("cvt.rna.tf32.f32 %0, %1;" : "=f"(o) : "f"(v));
    return o;
}

// perm-col = g*8 + q*2 + e  <->  k = g*8 + q + 4*e
__global__ void prep_weights(const float* __restrict__ w) {
    int idx = blockIdx.x * 256 + threadIdx.x;   // 0 .. 73727
    int kc  = idx >> 12;
    int rem = idx & 4095;
    int co  = rem >> 5;
    int col = rem & 31;
    int g = col >> 3, tt = col & 7, q = tt >> 1, e = tt & 1;
    int k  = g * 8 + q + 4 * e;
    int ci = ((kc & 1) << 5) + k;
    int rs = kc >> 1;
    g_A_pre[idx] = to_tf32(w[((size_t)co * CIN + ci) * 9 + rs]);
}

__global__ __launch_bounds__(256, 2)
void conv_mma(const float* __restrict__ x, float* __restrict__ out)
{
    __shared__ float  As[128 * A_STRIDE];   // 20480 B
    __shared__ float2 Bs[128 * B_KP];       // 17408 B  [n][kp], kp=q*4+g -> (k,k+4)

    const int tid  = threadIdx.x;
    const int wid  = tid >> 5;
    const int lane = tid & 31;
    const int wm   = wid >> 2;        // 0..1  (m half)
    const int wn   = wid & 3;         // 0..3  (n quarter)
    const int lr   = lane >> 2;       // 0..7
    const int lq   = lane & 3;        // 0..3

    const int ow0 = blockIdx.x * 64;
    const int oh0 = blockIdx.y * 2;
    const int bb  = blockIdx.z;

    float acc[4][4][4];
#pragma unroll
    for (int i = 0; i < 4; i++)
#pragma unroll
        for (int j = 0; j < 4; j++)
#pragma unroll
            for (int k = 0; k < 4; k++) acc[i][j][k] = 0.0f;

    const float* xb = x + (size_t)bb * CIN * H * W;

    for (int kc = 0; kc < NCHUNK; ++kc) {
        const int rs  = kc >> 1;
        const int r   = rs / 3;
        const int s   = rs - r * 3;
        const int ci0 = (kc & 1) << 5;

        __syncthreads();   // previous chunk's compute done before overwrite

        // ---- A: copy pre-permuted chunk (float4) ----
        {
            const float4* src = (const float4*)(g_A_pre + kc * 4096);
#pragma unroll
            for (int i = 0; i < 4; ++i) {
                int idx = tid + 256 * i;              // float4 index, 0..1023
                float4 v = src[idx];
                *(float4*)(As + (idx >> 3) * A_STRIDE + (idx & 7) * 4) = v;
            }
        }

        // ---- B: im2col gather, paired (k, k+4) per thread -> STS.64 ----
        {
#pragma unroll
            for (int i = 0; i < 8; ++i) {
                int flat = tid + 256 * i;             // 0..2047
                int n    = flat & 127;
                int pf   = flat >> 7;                 // 0..15 = kp = q*4 + g
                int q    = pf >> 2;
                int g    = pf & 3;
                int k0   = g * 8 + q;
                int c    = n & 63;
                int osub = n >> 6;
                int iw   = ow0 + c + s;
                int ih   = oh0 + osub + r;
                float v0 = 0.0f, v1 = 0.0f;
                if (iw < W) {
                    const float* p = xb + ((size_t)(ci0 + k0) * H + ih) * W + iw;
                    v0 = to_tf32(p[0]);
                    v1 = to_tf32(p[4 * H * W]);       // k0 + 4
                }
                Bs[n * B_KP + pf] = make_float2(v0, v1);
            }
        }

        __syncthreads();

        // ---- compute: 4 k8-groups x (4 m-frags x 4 n-frags) mma ----
#pragma unroll
        for (int g = 0; g < 4; ++g) {
            uint32_t a[4][4];
#pragma unroll
            for (int mf = 0; mf < 4; ++mf) {
                int row = wm * 64 + mf * 16 + lr;
                float2 v02 = *(const float2*)(As + row * A_STRIDE + g * 8 + lq * 2);
                float2 v13 = *(const float2*)(As + (row + 8) * A_STRIDE + g * 8 + lq * 2);
                a[mf][0] = __float_as_uint(v02.x);
                a[mf][1] = __float_as_uint(v13.x);
                a[mf][2] = __float_as_uint(v02.y);
                a[mf][3] = __float_as_uint(v13.y);
            }
            uint32_t b[4][2];
#pragma unroll
            for (int nf = 0; nf < 4; ++nf) {
                float2 v = Bs[(wn * 32 + nf * 8 + lr) * B_KP + lq * 4 + g];
                b[nf][0] = __float_as_uint(v.x);
                b[nf][1] = __float_as_uint(v.y);
            }
#pragma unroll
            for (int mf = 0; mf < 4; ++mf)
#pragma unroll
                for (int nf = 0; nf < 4; ++nf) {
                    asm volatile(
                        "mma.sync.aligned.m16n8k8.row.col.f32.tf32.tf32.f32 "
                        "{%0,%1,%2,%3}, {%4,%5,%6,%7}, {%8,%9}, {%0,%1,%2,%3};"
                        : "+f"(acc[mf][nf][0]), "+f"(acc[mf][nf][1]),
                          "+f"(acc[mf][nf][2]), "+f"(acc[mf][nf][3])
                        : "r"(a[mf][0]), "r"(a[mf][1]), "r"(a[mf][2]), "r"(a[mf][3]),
                          "r"(b[nf][0]), "r"(b[nf][1]));
                }
        }
    }

    // ---- epilogue: direct STG.64 (even ow, pairs in-bounds) ----
#pragma unroll
    for (int mf = 0; mf < 4; ++mf) {
#pragma unroll
        for (int nf = 0; nf < 4; ++nf) {
            int nglob = wn * 32 + nf * 8 + lq * 2;    // even
            int osub  = nglob >> 6;
            int ow    = ow0 + (nglob & 63);
            int oh    = oh0 + osub;
            if (ow < OW) {
                int co0 = wm * 64 + mf * 16 + lr;
                float* p0 = out + (((size_t)bb * COUT + co0) * OH + oh) * OW + ow;
                *(float2*)p0 = make_float2(acc[mf][nf][0], acc[mf][nf][1]);
                float* p1 = p0 + (size_t)8 * OH * OW;
                *(float2*)p1 = make_float2(acc[mf][nf][2], acc[mf][nf][3]);
            }
        }
    }
}

} // namespace

extern "C" void kernel_launch(void* const* d_in, const int* in_sizes, int n_in,
                              void* d_out, int out_size)
{
    const float* x = (const float*)d_in[0];
    const float* w = (const float*)d_in[1];
    float* out = (float*)d_out;

    prep_weights<<<NCHUNK * 4096 / 256, 256>>>(w);

    dim3 grid(2, 55, 32);   // ow tiles (2x64), oh pairs, batch
    conv_mma<<<grid, 256>>>(x, out);
}

// round 13
// speedup vs baseline: 2.2425x; 1.0572x over previous
#include <cuda_runtime.h>
#include <cstdint>

// Conv2d VALID: x[32,64,112,112] f32, w[128,64,3,3] f32 -> out[32,128,110,110] f32
// Implicit GEMM via mma.sync.m16n8k8 tf32.
// Round 13: R12 conflict-free skeleton + software pipeline:
//   - per-thread gather addresses hoisted (n = tid&127 is chunk-invariant)
//   - B chunk kc+1 prefetched into 16 regs during compute of kc, STS'd after
//   - A chunk copied by cp.async into double-buffered smem
//   - ONE barrier per chunk (was 2)

namespace {

constexpr int CIN = 64, COUT = 128, H = 112, W = 112, OH = 110, OW = 110;
constexpr int HW = H * W;
constexpr int NCHUNK = 18;
constexpr int A_STRIDE = 40;              // pair-bank (4*lr+lq) bijective
constexpr int B_KP = 17;                  // pair-bank (8nf+lr+4lq+g) bijective
constexpr int A_BYTES = 128 * A_STRIDE * 4;    // 20480
constexpr int B_BYTES = 128 * B_KP * 8;        // 17408
constexpr int SM_TOTAL = 2 * A_BYTES + 2 * B_BYTES;  // 75776

__device__ float g_A_pre[NCHUNK * 4096];  // [kc][co 128][perm-col 32] tf32

__device__ __forceinline__ float to_tf32(float v) {
    float o;
    asm("cvt.rna.tf32.f32 %0, %1;" : "=f"(o) : "f"(v));
    return o;
}
__device__ __forceinline__ uint32_t smem_u32(const void* p) {
    uint32_t a;
    asm("{ .reg .u64 t; cvta.to.shared.u64 t, %1; cvt.u32.u64 %0, t; }" : "=r"(a) : "l"(p));
    return a;
}
__device__ __forceinline__ void cp_async16(uint32_t dst, const void* src) {
    asm volatile("cp.async.ca.shared.global [%0], [%1], 16;" :: "r"(dst), "l"(src));
}
__device__ __forceinline__ void cp_commit() {
    asm volatile("cp.async.commit_group;" ::: "memory");
}
__device__ __forceinline__ void cp_wait0() {
    asm volatile("cp.async.wait_group 0;" ::: "memory");
}

// perm-col = g*8 + q*2 + e  <->  k = g*8 + q + 4*e
__global__ void prep_weights(const float* __restrict__ w) {
    int idx = blockIdx.x * 256 + threadIdx.x;   // 0 .. 73727
    int kc  = idx >> 12;
    int rem = idx & 4095;
    int co  = rem >> 5;
    int col = rem & 31;
    int g = col >> 3, tt = col & 7, q = tt >> 1, e = tt & 1;
    int k  = g * 8 + q + 4 * e;
    int ci = ((kc & 1) << 5) + k;
    int rs = kc >> 1;
    g_A_pre[idx] = to_tf32(w[((size_t)co * CIN + ci) * 9 + rs]);
}

__global__ __launch_bounds__(256, 2)
void conv_mma(const float* __restrict__ x, float* __restrict__ out)
{
    extern __shared__ char sm[];
    // layout: A0 | A1 | B0 | B1

    const int tid  = threadIdx.x;
    const int lane = tid & 31;
    const int wid  = tid >> 5;
    const int wm   = wid >> 2;
    const int wn   = wid & 3;
    const int lr   = lane >> 2;
    const int lq   = lane & 3;

    const int ow0 = blockIdx.x * 64;
    const int oh0 = blockIdx.y * 2;
    const int bb  = blockIdx.z;

    const float* xb = x + (size_t)bb * CIN * HW;

    // ---- chunk-invariant gather constants (n = tid & 127) ----
    const int n_    = tid & 127;
    const int t2    = tid >> 7;            // 0..1
    const int c_    = n_ & 63;
    const int osub_ = n_ >> 6;
    // pf_i = t2 + 2*i ; q = pf>>2 ; g = pf&3 ; k0 = g*8+q
    uint32_t offc[8];
#pragma unroll
    for (int i = 0; i < 8; ++i) {
        int pf = t2 + 2 * i;
        int k0 = (pf & 3) * 8 + (pf >> 2);
        offc[i] = (uint32_t)(k0 * HW + osub_ * W + c_);
    }
    const uint32_t bsts = smem_u32(sm + 2 * A_BYTES) +
                          (uint32_t)(n_ * B_KP + t2) * 8;   // Bs[n][pf] base (pf step 2 -> +16B)

    float acc[4][4][4];
#pragma unroll
    for (int i = 0; i < 4; i++)
#pragma unroll
        for (int j = 0; j < 4; j++)
#pragma unroll
            for (int k = 0; k < 4; k++) acc[i][j][k] = 0.0f;

    // ---- A cp.async dst addresses (4 x 16B per thread) ----
    uint32_t a_dst[4];
#pragma unroll
    for (int i = 0; i < 4; ++i) {
        int idx = tid + 256 * i;
        a_dst[i] = smem_u32(sm) + (uint32_t)((idx >> 3) * A_STRIDE + (idx & 7) * 4) * 4;
    }

    // ---- prologue: B chunk 0 gather+STS, A chunk 0 cp.async ----
    float pv0[8], pv1[8];
    {
        const int base0 = oh0 * W + ow0;   // kc=0: r=0,s=0,ci0=0
        const bool pred = (ow0 + c_) < W;  // s=0
#pragma unroll
        for (int i = 0; i < 8; ++i) {
            pv0[i] = 0.0f; pv1[i] = 0.0f;
            if (pred) {
                pv0[i] = xb[base0 + (int)offc[i]];
                pv1[i] = xb[base0 + (int)offc[i] + 4 * HW];
            }
        }
        float2* bp = (float2*)(sm + 2 * A_BYTES);
#pragma unroll
        for (int i = 0; i < 8; ++i)
            bp[n_ * B_KP + t2 + 2 * i] = make_float2(to_tf32(pv0[i]), to_tf32(pv1[i]));

        const float4* src = (const float4*)g_A_pre;
#pragma unroll
        for (int i = 0; i < 4; ++i) cp_async16(a_dst[i], src + tid + 256 * i);
        cp_commit();
    }

    for (int kc = 0; kc < NCHUNK; ++kc) {
        const int buf = kc & 1;

        cp_wait0();
        __syncthreads();   // A[buf] + B[buf] ready; prior compute done

        // ---- issue prefetches for chunk kc+1 ----
        if (kc < NCHUNK - 1) {
            const int kn  = kc + 1;
            const int rsn = kn >> 1;
            const int rn  = rsn / 3;
            const int sn  = rsn - rn * 3;
            const int cin = (kn & 1) << 5;
            const int base = cin * HW + (oh0 + rn) * W + ow0 + sn;
            const bool pred = (ow0 + c_ + sn) < W;
#pragma unroll
            for (int i = 0; i < 8; ++i) {
                pv0[i] = 0.0f; pv1[i] = 0.0f;
                if (pred) {
                    pv0[i] = xb[base + (int)offc[i]];
                    pv1[i] = xb[base + (int)offc[i] + 4 * HW];
                }
            }
            const float4* src = (const float4*)(g_A_pre + kn * 4096);
            const uint32_t abase = (kn & 1) ? (uint32_t)A_BYTES : 0u;
#pragma unroll
            for (int i = 0; i < 4; ++i) cp_async16(a_dst[i] + abase, src + tid + 256 * i);
            cp_commit();
        }

        // ---- compute chunk kc ----
        const float*  As = (const float*)(sm + buf * A_BYTES);
        const float2* Bs = (const float2*)(sm + 2 * A_BYTES + buf * B_BYTES);

#pragma unroll
        for (int g = 0; g < 4; ++g) {
            uint32_t a[4][4];
#pragma unroll
            for (int mf = 0; mf < 4; ++mf) {
                int row = wm * 64 + mf * 16 + lr;
                float2 v02 = *(const float2*)(As + row * A_STRIDE + g * 8 + lq * 2);
                float2 v13 = *(const float2*)(As + (row + 8) * A_STRIDE + g * 8 + lq * 2);
                a[mf][0] = __float_as_uint(v02.x);
                a[mf][1] = __float_as_uint(v13.x);
                a[mf][2] = __float_as_uint(v02.y);
                a[mf][3] = __float_as_uint(v13.y);
            }
            uint32_t b[4][2];
#pragma unroll
            for (int nf = 0; nf < 4; ++nf) {
                float2 v = Bs[(wn * 32 + nf * 8 + lr) * B_KP + lq * 4 + g];
                b[nf][0] = __float_as_uint(v.x);
                b[nf][1] = __float_as_uint(v.y);
            }
#pragma unroll
            for (int mf = 0; mf < 4; ++mf)
#pragma unroll
                for (int nf = 0; nf < 4; ++nf) {
                    asm volatile(
                        "mma.sync.aligned.m16n8k8.row.col.f32.tf32.tf32.f32 "
                        "{%0,%1,%2,%3}, {%4,%5,%6,%7}, {%8,%9}, {%0,%1,%2,%3};"
                        : "+f"(acc[mf][nf][0]), "+f"(acc[mf][nf][1]),
                          "+f"(acc[mf][nf][2]), "+f"(acc[mf][nf][3])
                        : "r"(a[mf][0]), "r"(a[mf][1]), "r"(a[mf][2]), "r"(a[mf][3]),
                          "r"(b[nf][0]), "r"(b[nf][1]));
                }
        }

        // ---- store prefetched B into other buffer (visible after next sync) ----
        if (kc < NCHUNK - 1) {
            const uint32_t bdst = bsts + ((kc + 1) & 1 ? (uint32_t)B_BYTES : 0u);
#pragma unroll
            for (int i = 0; i < 8; ++i) {
                float w0 = to_tf32(pv0[i]);
                float w1 = to_tf32(pv1[i]);
                asm volatile("st.shared.v2.f32 [%0], {%1, %2};"
                             :: "r"(bdst + (uint32_t)(16 * i)), "f"(w0), "f"(w1) : "memory");
            }
        }
    }

    // ---- epilogue: direct STG.64 (even ow, pairs in-bounds) ----
#pragma unroll
    for (int mf = 0; mf < 4; ++mf) {
#pragma unroll
        for (int nf = 0; nf < 4; ++nf) {
            int nglob = wn * 32 + nf * 8 + lq * 2;    // even
            int osub  = nglob >> 6;
            int ow    = ow0 + (nglob & 63);
            int oh    = oh0 + osub;
            if (ow < OW) {
                int co0 = wm * 64 + mf * 16 + lr;
                float* p0 = out + (((size_t)bb * COUT + co0) * OH + oh) * OW + ow;
                *(float2*)p0 = make_float2(acc[mf][nf][0], acc[mf][nf][1]);
                float* p1 = p0 + (size_t)8 * OH * OW;
                *(float2*)p1 = make_float2(acc[mf][nf][2], acc[mf][nf][3]);
            }
        }
    }
}

} // namespace

extern "C" void kernel_launch(void* const* d_in, const int* in_sizes, int n_in,
                              void* d_out, int out_size)
{
    const float* x = (const float*)d_in[0];
    const float* w = (const float*)d_in[1];
    float* out = (float*)d_out;

    cudaFuncSetAttribute(conv_mma, cudaFuncAttributeMaxDynamicSharedMemorySize, SM_TOTAL);

    prep_weights<<<NCHUNK * 4096 / 256, 256>>>(w);

    dim3 grid(2, 55, 32);   // ow tiles (2x64), oh pairs, batch
    conv_mma<<<grid, 256, SM_TOTAL>>>(x, out);
}